// round 15
// baseline (speedup 1.0000x reference)
#include <cuda_runtime.h>
#include <cuda_bf16.h>
#include <cstdint>

#define BB 2
#define NN 2048
#define DIN 512
#define HH 8
#define FF 64
#define HF 512
#define TILES 16
#define LOG2E 1.4426950408889634f

__device__ __nv_bfloat16 g_nodes_bf[(size_t)BB*NN*DIN];
__device__ __nv_bfloat16 g_w_bf[DIN*HF];
__device__ __nv_bfloat16 g_mapped_bf[(size_t)BB*NN*HF];
__device__ float2 g_el2[BB*NN*HH];   // (2^el, 2^{0.2 el})  [b][n][h]
__device__ float2 g_er2[BB*NN*HH];   // (2^er, 2^{0.2 er})
__device__ float g_hout[(size_t)BB*HH*NN*FF];
__device__ __align__(16) unsigned char g_ebit[(size_t)BB*NN*(NN/8)];  // 1 bit/edge

__device__ __forceinline__ uint32_t smem_u32(const void* p){
    uint32_t a; asm("{ .reg .u64 t; cvta.to.shared.u64 t, %1; cvt.u32.u64 %0, t; }" : "=r"(a) : "l"(p)); return a;
}

#define MMA(c, a, b0, b1) asm volatile( \
    "mma.sync.aligned.m16n8k16.row.col.f32.bf16.bf16.f32 " \
    "{%0,%1,%2,%3}, {%4,%5,%6,%7}, {%8,%9}, {%0,%1,%2,%3};" \
    : "+f"((c)[0]), "+f"((c)[1]), "+f"((c)[2]), "+f"((c)[3]) \
    : "r"((a)[0]), "r"((a)[1]), "r"((a)[2]), "r"((a)[3]), "r"(b0), "r"(b1))

#define LDSM4(r, addr) asm volatile( \
    "ldmatrix.sync.aligned.m8n8.x4.shared.b16 {%0,%1,%2,%3}, [%4];" \
    : "=r"((r)[0]), "=r"((r)[1]), "=r"((r)[2]), "=r"((r)[3]) : "r"(addr))

#define LDSM4T(r, addr) asm volatile( \
    "ldmatrix.sync.aligned.m8n8.x4.trans.shared.b16 {%0,%1,%2,%3}, [%4];" \
    : "=r"((r)[0]), "=r"((r)[1]), "=r"((r)[2]), "=r"((r)[3]) : "r"(addr))

// ---------------- f32 -> bf16 input packs --------------------------------------
__global__ __launch_bounds__(256) void cvt_nodes_kernel(const float4* __restrict__ src) {
    int i = blockIdx.x * 256 + threadIdx.x;
    float4 v = src[i];
    uint2 o;
    asm("cvt.rn.bf16x2.f32 %0, %1, %2;" : "=r"(o.x) : "f"(v.y), "f"(v.x));
    asm("cvt.rn.bf16x2.f32 %0, %1, %2;" : "=r"(o.y) : "f"(v.w), "f"(v.z));
    ((uint2*)g_nodes_bf)[i] = o;
}
__global__ __launch_bounds__(256) void cvt_w_kernel(const float4* __restrict__ src) {
    int i = blockIdx.x * 256 + threadIdx.x;
    float4 v = src[i];
    uint2 o;
    asm("cvt.rn.bf16x2.f32 %0, %1, %2;" : "=r"(o.x) : "f"(v.y), "f"(v.x));
    asm("cvt.rn.bf16x2.f32 %0, %1, %2;" : "=r"(o.y) : "f"(v.w), "f"(v.z));
    ((uint2*)g_w_bf)[i] = o;
}

// ---------------- GEMM: mapped = nodes @ W via HMMA bf16 (bf16 out) -----------
__global__ __launch_bounds__(256) void gemm_hmma_kernel(void) {
    __shared__ __align__(16) char smA[16384];
    __shared__ __align__(16) char smB[8192];
    const uint32_t sa = smem_u32(smA), sbm = smem_u32(smB);
    const int tid = threadIdx.x, w = tid >> 5, lane = tid & 31;
    const int bn = blockIdx.x * 64, bm = blockIdx.y * 128;
    const int mbase = (w & 3) * 32, nbase = (w >> 2) * 32;
    const int g = lane >> 2, t = lane & 3;

    float c[2][4][4];
#pragma unroll
    for (int mi = 0; mi < 2; mi++)
#pragma unroll
        for (int ng = 0; ng < 4; ng++)
#pragma unroll
            for (int r = 0; r < 4; r++) c[mi][ng][r] = 0.f;

    const int arow0 = lane & 15, akh = lane >> 4;
    const int joff = ((lane >> 3) & 1) * 8 + (lane & 7);
    const int fmb  = (lane >> 4) * 8;
    const uint32_t swb = (uint32_t)((lane & 7) << 4);

    for (int kc = 0; kc < 8; kc++) {
        const int k0 = kc * 64;
        __syncthreads();
        {
            const int row = tid >> 1, half = tid & 1;
            const uint4* src = (const uint4*)(g_nodes_bf + (size_t)(bm + row) * DIN + k0 + half * 32);
            uint4 v0 = src[0], v1 = src[1], v2 = src[2], v3 = src[3];
            const uint32_t sw = (uint32_t)((row & 7) << 4);
            char* rbase = smA + row * 128;
            *(uint4*)(rbase + (((uint32_t)(half*64 + 0))  ^ sw)) = v0;
            *(uint4*)(rbase + (((uint32_t)(half*64 + 16)) ^ sw)) = v1;
            *(uint4*)(rbase + (((uint32_t)(half*64 + 32)) ^ sw)) = v2;
            *(uint4*)(rbase + (((uint32_t)(half*64 + 48)) ^ sw)) = v3;
        }
        {
            const int krow = tid >> 2, q4 = tid & 3;
            const uint4* src = (const uint4*)(g_w_bf + (size_t)(k0 + krow) * HF + bn + q4 * 16);
            uint4 v0 = src[0], v1 = src[1];
            const uint32_t sw = (uint32_t)((krow & 7) << 4);
            char* rbase = smB + krow * 128;
            *(uint4*)(rbase + (((uint32_t)(q4*32 + 0))  ^ sw)) = v0;
            *(uint4*)(rbase + (((uint32_t)(q4*32 + 16)) ^ sw)) = v1;
        }
        __syncthreads();

#pragma unroll
        for (int kk = 0; kk < 4; kk++) {
            uint32_t ah[2][4];
#pragma unroll
            for (int mi = 0; mi < 2; mi++) {
                const int arow = mbase + mi * 16 + arow0;
                uint32_t addr = sa + (uint32_t)arow * 128u +
                    (((uint32_t)(kk * 32 + akh * 16)) ^ ((uint32_t)(arow & 7) << 4));
                LDSM4(ah[mi], addr);
            }
            uint32_t rowb = sbm + (uint32_t)(kk * 16 + joff) * 128u;
#pragma unroll
            for (int li = 0; li < 2; li++) {
                uint32_t b4[4];
                uint32_t off = ((uint32_t)((nbase + fmb + li * 16) * 2)) ^ swb;
                LDSM4T(b4, rowb + off);
                MMA(c[0][li*2],     ah[0], b4[0], b4[1]);
                MMA(c[1][li*2],     ah[1], b4[0], b4[1]);
                MMA(c[0][li*2 + 1], ah[0], b4[2], b4[3]);
                MMA(c[1][li*2 + 1], ah[1], b4[2], b4[3]);
            }
        }
    }
#pragma unroll
    for (int mi = 0; mi < 2; mi++)
#pragma unroll
        for (int u = 0; u < 2; u++) {
            const int row = bm + mbase + mi * 16 + u * 8 + g;
#pragma unroll
            for (int ng = 0; ng < 4; ng++) {
                const int col = bn + nbase + ng * 8 + 2 * t;
                uint32_t o;
                asm("cvt.rn.bf16x2.f32 %0, %1, %2;" : "=r"(o)
                    : "f"(c[mi][ng][u*2 + 1]), "f"(c[mi][ng][u*2 + 0]));
                *(uint32_t*)(g_mapped_bf + (size_t)row * HF + col) = o;
            }
        }
}

// ---------------- el/er -> factored exp tables ---------------------------------
__global__ __launch_bounds__(256) void elr_kernel(const float* __restrict__ a) {
    int gid = blockIdx.x * 256 + threadIdx.x;       // over 2*B*N*H
    if (gid >= 2 * BB * NN * HH) return;
    int idx = gid >> 1, half = gid & 1;
    const uint32_t* mp = (const uint32_t*)(g_mapped_bf + (size_t)idx * FF) + half * 16;
    float el = 0.f, er = 0.f;
#pragma unroll
    for (int q = 0; q < 16; q++) {
        uint32_t u = mp[q];
        float lo = __uint_as_float(u << 16);
        float hi = __uint_as_float(u & 0xFFFF0000u);
        int f = half * 32 + 2 * q;
        el += lo * a[f] + hi * a[f + 1];
        er += lo * a[FF + f] + hi * a[FF + f + 1];
    }
    el += __shfl_xor_sync(0xffffffffu, el, 1);
    er += __shfl_xor_sync(0xffffffffu, er, 1);
    if (half == 0) {
        float elx = el * LOG2E, erx = er * LOG2E;
        float elp, eln, erp, ern;
        asm("ex2.approx.f32 %0, %1;" : "=f"(elp) : "f"(elx));
        asm("ex2.approx.f32 %0, %1;" : "=f"(eln) : "f"(0.2f * elx));
        asm("ex2.approx.f32 %0, %1;" : "=f"(erp) : "f"(erx));
        asm("ex2.approx.f32 %0, %1;" : "=f"(ern) : "f"(0.2f * erx));
        g_el2[idx] = make_float2(elp, eln);
        g_er2[idx] = make_float2(erp, ern);
    }
}

// ---------------- pack edges int32 -> bits -------------------------------------
__global__ __launch_bounds__(256) void pack_edge_bits_kernel(const int* __restrict__ e) {
    int gid = blockIdx.x * 256 + threadIdx.x;       // BB*NN*NN/128 chunks
    size_t base = (size_t)gid * 128;
    uint32_t m[4];
#pragma unroll
    for (int w = 0; w < 4; w++) {
        uint32_t mm = 0;
#pragma unroll
        for (int k = 0; k < 8; k++) {
            int4 v = *(const int4*)(e + base + w * 32 + k * 4);
            mm |= (uint32_t)((v.x ? 1u : 0u) | ((v.y ? 1u : 0u) << 1) |
                             ((v.z ? 1u : 0u) << 2) | ((v.w ? 1u : 0u) << 3)) << (k * 4);
        }
        m[w] = mm;
    }
    uint4 o; o.x = m[0]; o.y = m[1]; o.z = m[2]; o.w = m[3];
    *(uint4*)(g_ebit + (size_t)gid * 16) = o;
}

// ---------------- attention --------------------------------------------------
// grid (16, 2, 8), 256 thr, 8 warps. warp = (i-quarter q = w&3 -> 32 rows,
// j-half jh = w>>2 -> 64 of 128 j). Per tk (4 per tile): 4 u16 bit loads,
// 2 float4 er loads, 8 PP (no exp: p = max(Elp*Erp, Eln*Ern), exact),
// 4 LDSM (shared by 2 mi), 16 MMA. Epilogue: jh=1 dumps c to smem (reusing V
// region), jh=0 adds + normalizes + stores.
#define SV    0          // 128j x 64f bf16 = 16384
#define SEB   16384      // 128 rows x 16B bits = 2048
#define SER   18432      // 128 x float2 (Erp,Ern) = 1024
#define SRED  0          // epilogue: 128 rows x 66 words = 33792 (reuses SV/SEB)
#define SLS   33792      // 2 x 128 floats = 1024
#define SM_AT 34816

#define PP(DH, LP, LN, ER4, B0, B1, LACC) do{                                 \
    float p0 = fmaxf((LP) * (ER4).x, (LN) * (ER4).y);                         \
    float p1 = fmaxf((LP) * (ER4).z, (LN) * (ER4).w);                         \
    p0 = (B0) ? p0 : 0.f;                                                     \
    p1 = (B1) ? p1 : 0.f;                                                     \
    (LACC) += p0 + p1;                                                        \
    asm("cvt.rn.bf16x2.f32 %0, %1, %2;" : "=r"(DH) : "f"(p1), "f"(p0));       \
} while(0)

__global__ __launch_bounds__(256) void attn_hmma_kernel(void) {
    extern __shared__ char smem[];
    const uint32_t sb = smem_u32(smem);
    const int tid = threadIdx.x, w = tid >> 5, lane = tid & 31;
    const int b = blockIdx.y, i0 = blockIdx.x * 128, head = blockIdx.z;
    const int q = w & 3, jh = w >> 2;
    const int ib = q * 32;
    const int g = lane >> 2, t = lane & 3;

    float elp_r[2][2], eln_r[2][2];
#pragma unroll
    for (int mi = 0; mi < 2; mi++)
#pragma unroll
        for (int u = 0; u < 2; u++) {
            float2 v = g_el2[((size_t)b*NN + i0 + ib + mi*16 + u*8 + g)*HH + head];
            elp_r[mi][u] = v.x; eln_r[mi][u] = v.y;
        }

    float c[2][8][4];
    float l_acc[4] = {0.f, 0.f, 0.f, 0.f};
#pragma unroll
    for (int mi = 0; mi < 2; mi++)
#pragma unroll
        for (int ng = 0; ng < 8; ng++)
#pragma unroll
            for (int r = 0; r < 4; r++) c[mi][ng][r] = 0.f;

    const int joff = ((lane >> 3) & 1) * 8 + (lane & 7);
    const int fmb  = (lane >> 4) * 8;
    const uint32_t sw = (uint32_t)((lane & 7) << 4);

    for (int tt = 0; tt < TILES; tt++) {
        const int j0 = tt * 128;
        __syncthreads();
        {   // stage V: 128j x 64f bf16 copy, swizzled 128B rows
            const int j = tid >> 1, fh = (tid & 1) * 32;
            const uint4* src = (const uint4*)(g_mapped_bf + ((size_t)b*NN + j0 + j)*HF + head*FF + fh);
            const uint32_t swj = (uint32_t)((j & 7) << 4);
#pragma unroll
            for (int q8 = 0; q8 < 4; q8++) {
                uint4 v = src[q8];
                uint32_t off = ((uint32_t)(fh*2 + q8*16)) ^ swj;
                *(uint4*)(smem + SV + j*128 + off) = v;
            }
        }
        if (tid < 128) {   // stage edge bits: 128 rows x 16B
            const uint4* esrc = (const uint4*)(g_ebit + ((size_t)b*NN + i0 + tid)*(NN/8) + tt*16);
            *(uint4*)(smem + SEB + tid*16) = esrc[0];
        }
        if (tid < 128) {   // stage er pair table
            float2 v = g_er2[((size_t)b*NN + j0 + tid)*HH + head];
            *(float2*)(smem + SER + tid*8) = v;
        }
        __syncthreads();

#pragma unroll
        for (int tk = 0; tk < 4; tk++) {
            const int j0k = jh * 64 + tk * 16;
            float4 erA = *(const float4*)(smem + SER + (j0k + 2*t)*8);
            float4 erB = *(const float4*)(smem + SER + (j0k + 8 + 2*t)*8);
            uint32_t ah[2][4];
#pragma unroll
            for (int mi = 0; mi < 2; mi++) {
                uint32_t ea = sb + SEB + (uint32_t)((ib + mi*16 + g)*16 + (j0k >> 3));
                uint32_t m0, m1;
                asm volatile("ld.shared.u16 %0, [%1];"      : "=r"(m0) : "r"(ea));
                asm volatile("ld.shared.u16 %0, [%1+128];"  : "=r"(m1) : "r"(ea));
                PP(ah[mi][0], elp_r[mi][0], eln_r[mi][0], erA,
                   (m0 >> (2*t)) & 1u,   (m0 >> (2*t+1)) & 1u,   l_acc[mi*2 + 0]);
                PP(ah[mi][1], elp_r[mi][1], eln_r[mi][1], erA,
                   (m1 >> (2*t)) & 1u,   (m1 >> (2*t+1)) & 1u,   l_acc[mi*2 + 1]);
                PP(ah[mi][2], elp_r[mi][0], eln_r[mi][0], erB,
                   (m0 >> (8+2*t)) & 1u, (m0 >> (9+2*t)) & 1u,   l_acc[mi*2 + 0]);
                PP(ah[mi][3], elp_r[mi][1], eln_r[mi][1], erB,
                   (m1 >> (8+2*t)) & 1u, (m1 >> (9+2*t)) & 1u,   l_acc[mi*2 + 1]);
            }
            uint32_t rowb = sb + SV + (uint32_t)(j0k + joff)*128u;
#pragma unroll
            for (int li = 0; li < 4; li++) {
                uint32_t b4[4];
                uint32_t off = ((uint32_t)((fmb + li*16)*2)) ^ sw;
                LDSM4T(b4, rowb + off);
                MMA(c[0][li*2],     ah[0], b4[0], b4[1]);
                MMA(c[0][li*2 + 1], ah[0], b4[2], b4[3]);
                MMA(c[1][li*2],     ah[1], b4[0], b4[1]);
                MMA(c[1][li*2 + 1], ah[1], b4[2], b4[3]);
            }
        }
    }

    // ---- epilogue ----
    float lsum[4];
#pragma unroll
    for (int k = 0; k < 4; k++) {
        float l = l_acc[k];
        l += __shfl_xor_sync(0xffffffffu, l, 1);
        l += __shfl_xor_sync(0xffffffffu, l, 2);
        lsum[k] = l;
    }
    __syncthreads();   // everyone done reading SV/SEB/SER
    if (t == 0) {
#pragma unroll
        for (int mi = 0; mi < 2; mi++)
#pragma unroll
            for (int u = 0; u < 2; u++)
                ((float*)(smem + SLS))[jh*128 + ib + mi*16 + u*8 + g] = lsum[mi*2 + u];
    }
    if (jh == 1) {
#pragma unroll
        for (int mi = 0; mi < 2; mi++)
#pragma unroll
            for (int u = 0; u < 2; u++) {
                const int row = ib + mi*16 + u*8 + g;
#pragma unroll
                for (int ng = 0; ng < 8; ng++) {
                    float2 v; v.x = c[mi][ng][u*2 + 0]; v.y = c[mi][ng][u*2 + 1];
                    *(float2*)(smem + SRED + row*264 + (ng*8 + 2*t)*4) = v;
                }
            }
    }
    __syncthreads();
    if (jh == 0) {
        const float* sl = (const float*)(smem + SLS);
#pragma unroll
        for (int mi = 0; mi < 2; mi++)
#pragma unroll
            for (int u = 0; u < 2; u++) {
                const int row = ib + mi*16 + u*8 + g;
                const float linv = 1.f / (sl[row] + sl[128 + row]);
                float* dst = g_hout + (((size_t)b*HH + head)*NN + i0 + row)*FF + 2*t;
#pragma unroll
                for (int ng = 0; ng < 8; ng++) {
                    float2 o = *(const float2*)(smem + SRED + row*264 + (ng*8 + 2*t)*4);
                    o.x = (o.x + c[mi][ng][u*2 + 0]) * linv;
                    o.y = (o.y + c[mi][ng][u*2 + 1]) * linv;
                    *(float2*)(dst + ng*8) = o;
                }
            }
    }
}

// ---------------- combine: mean over heads + sigmoid ---------------------------
__global__ __launch_bounds__(256) void combine_kernel(float* __restrict__ out) {
    int idx = blockIdx.x * 256 + threadIdx.x;
    if (idx >= BB * NN * FF) return;
    int f = idx & 63;
    int bi = idx >> 6;
    int b = bi >> 11, i = bi & 2047;
    float s = 0.f;
#pragma unroll
    for (int h = 0; h < HH; h++)
        s += g_hout[(((size_t)b * HH + h) * NN + i) * FF + f];
    s *= 0.125f;
    out[idx] = 1.f / (1.f + __expf(-s));
}

// ---------------- launch -------------------------------------------------------
extern "C" void kernel_launch(void* const* d_in, const int* in_sizes, int n_in,
                              void* d_out, int out_size) {
    const float* nodes = (const float*)d_in[0];
    const int*   edges = (const int*)d_in[1];
    const float* W     = (const float*)d_in[2];
    const float* a     = (const float*)d_in[3];
    float* out = (float*)d_out;

    cvt_nodes_kernel<<<(BB*NN*DIN/4)/256, 256>>>((const float4*)nodes);
    cvt_w_kernel<<<(DIN*HF/4)/256, 256>>>((const float4*)W);

    dim3 ggrid(HF / 64, (BB * NN) / 128);    // (8, 32) = 256 CTAs
    gemm_hmma_kernel<<<ggrid, 256>>>();

    elr_kernel<<<(2 * BB * NN * HH + 255) / 256, 256>>>(a);

    pack_edge_bits_kernel<<<(BB * NN * NN / 128) / 256, 256>>>(edges);

    dim3 agrid(NN / 128, BB, HH);            // (16, 2, 8) = 256 CTAs
    attn_hmma_kernel<<<agrid, 256, SM_AT>>>();

    combine_kernel<<<(BB * NN * FF + 255) / 256, 256>>>(out);
}

// round 16
// speedup vs baseline: 1.3942x; 1.3942x over previous
#include <cuda_runtime.h>
#include <cuda_bf16.h>
#include <cstdint>

#define BB 2
#define NN 2048
#define DIN 512
#define HH 8
#define FF 64
#define HF 512
#define TILES 16
#define LOG2E 1.4426950408889634f

__device__ __nv_bfloat16 g_nodes_bf[(size_t)BB*NN*DIN];
__device__ __nv_bfloat16 g_w_bf[DIN*HF];
__device__ float g_mapped[(size_t)BB*NN*HF];
__device__ __nv_bfloat16 g_mapped_bf[(size_t)BB*NN*HF];
__device__ float g_el[BB*NN*HH];
__device__ float g_er_t[HH*BB*NN];          // transposed: [h][b][n], contiguous per head
__device__ float g_hout[(size_t)BB*HH*NN*FF];
__device__ __align__(16) unsigned char g_eb[(size_t)BB*NN*NN];

__device__ __forceinline__ uint32_t smem_u32(const void* p){
    uint32_t a; asm("{ .reg .u64 t; cvta.to.shared.u64 t, %1; cvt.u32.u64 %0, t; }" : "=r"(a) : "l"(p)); return a;
}

#define MMA(c, a, b0, b1) asm volatile( \
    "mma.sync.aligned.m16n8k16.row.col.f32.bf16.bf16.f32 " \
    "{%0,%1,%2,%3}, {%4,%5,%6,%7}, {%8,%9}, {%0,%1,%2,%3};" \
    : "+f"((c)[0]), "+f"((c)[1]), "+f"((c)[2]), "+f"((c)[3]) \
    : "r"((a)[0]), "r"((a)[1]), "r"((a)[2]), "r"((a)[3]), "r"(b0), "r"(b1))

#define LDSM4(r, addr) asm volatile( \
    "ldmatrix.sync.aligned.m8n8.x4.shared.b16 {%0,%1,%2,%3}, [%4];" \
    : "=r"((r)[0]), "=r"((r)[1]), "=r"((r)[2]), "=r"((r)[3]) : "r"(addr))

#define LDSM4T(r, addr) asm volatile( \
    "ldmatrix.sync.aligned.m8n8.x4.trans.shared.b16 {%0,%1,%2,%3}, [%4];" \
    : "=r"((r)[0]), "=r"((r)[1]), "=r"((r)[2]), "=r"((r)[3]) : "r"(addr))

#define CPA16(dst, src) asm volatile( \
    "cp.async.cg.shared.global [%0], [%1], 16;" :: "r"(dst), "l"(src) : "memory")
#define CPA_COMMIT() asm volatile("cp.async.commit_group;" ::: "memory")
#define CPA_WAIT1() asm volatile("cp.async.wait_group 1;" ::: "memory")
#define CPA_WAIT0() asm volatile("cp.async.wait_group 0;" ::: "memory")

// ---------------- f32 -> bf16 input packs --------------------------------------
__global__ __launch_bounds__(256) void cvt_nodes_kernel(const float4* __restrict__ src) {
    int i = blockIdx.x * 256 + threadIdx.x;
    float4 v = src[i];
    uint2 o;
    asm("cvt.rn.bf16x2.f32 %0, %1, %2;" : "=r"(o.x) : "f"(v.y), "f"(v.x));
    asm("cvt.rn.bf16x2.f32 %0, %1, %2;" : "=r"(o.y) : "f"(v.w), "f"(v.z));
    ((uint2*)g_nodes_bf)[i] = o;
}
__global__ __launch_bounds__(256) void cvt_w_kernel(const float4* __restrict__ src) {
    int i = blockIdx.x * 256 + threadIdx.x;
    float4 v = src[i];
    uint2 o;
    asm("cvt.rn.bf16x2.f32 %0, %1, %2;" : "=r"(o.x) : "f"(v.y), "f"(v.x));
    asm("cvt.rn.bf16x2.f32 %0, %1, %2;" : "=r"(o.y) : "f"(v.w), "f"(v.z));
    ((uint2*)g_w_bf)[i] = o;
}

// ---------------- GEMM: mapped = nodes @ W via HMMA bf16 (f32 + bf16 out) -----
__global__ __launch_bounds__(256) void gemm_hmma_kernel(void) {
    __shared__ __align__(16) char smA[16384];
    __shared__ __align__(16) char smB[8192];
    const uint32_t sa = smem_u32(smA), sbm = smem_u32(smB);
    const int tid = threadIdx.x, w = tid >> 5, lane = tid & 31;
    const int bn = blockIdx.x * 64, bm = blockIdx.y * 128;
    const int mbase = (w & 3) * 32, nbase = (w >> 2) * 32;
    const int g = lane >> 2, t = lane & 3;

    float c[2][4][4];
#pragma unroll
    for (int mi = 0; mi < 2; mi++)
#pragma unroll
        for (int ng = 0; ng < 4; ng++)
#pragma unroll
            for (int r = 0; r < 4; r++) c[mi][ng][r] = 0.f;

    const int arow0 = lane & 15, akh = lane >> 4;
    const int joff = ((lane >> 3) & 1) * 8 + (lane & 7);
    const int fmb  = (lane >> 4) * 8;
    const uint32_t swb = (uint32_t)((lane & 7) << 4);

    for (int kc = 0; kc < 8; kc++) {
        const int k0 = kc * 64;
        __syncthreads();
        {
            const int row = tid >> 1, half = tid & 1;
            const uint4* src = (const uint4*)(g_nodes_bf + (size_t)(bm + row) * DIN + k0 + half * 32);
            uint4 v0 = src[0], v1 = src[1], v2 = src[2], v3 = src[3];
            const uint32_t sw = (uint32_t)((row & 7) << 4);
            char* rbase = smA + row * 128;
            *(uint4*)(rbase + (((uint32_t)(half*64 + 0))  ^ sw)) = v0;
            *(uint4*)(rbase + (((uint32_t)(half*64 + 16)) ^ sw)) = v1;
            *(uint4*)(rbase + (((uint32_t)(half*64 + 32)) ^ sw)) = v2;
            *(uint4*)(rbase + (((uint32_t)(half*64 + 48)) ^ sw)) = v3;
        }
        {
            const int krow = tid >> 2, q4 = tid & 3;
            const uint4* src = (const uint4*)(g_w_bf + (size_t)(k0 + krow) * HF + bn + q4 * 16);
            uint4 v0 = src[0], v1 = src[1];
            const uint32_t sw = (uint32_t)((krow & 7) << 4);
            char* rbase = smB + krow * 128;
            *(uint4*)(rbase + (((uint32_t)(q4*32 + 0))  ^ sw)) = v0;
            *(uint4*)(rbase + (((uint32_t)(q4*32 + 16)) ^ sw)) = v1;
        }
        __syncthreads();

#pragma unroll
        for (int kk = 0; kk < 4; kk++) {
            uint32_t ah[2][4];
#pragma unroll
            for (int mi = 0; mi < 2; mi++) {
                const int arow = mbase + mi * 16 + arow0;
                uint32_t addr = sa + (uint32_t)arow * 128u +
                    (((uint32_t)(kk * 32 + akh * 16)) ^ ((uint32_t)(arow & 7) << 4));
                LDSM4(ah[mi], addr);
            }
            uint32_t rowb = sbm + (uint32_t)(kk * 16 + joff) * 128u;
#pragma unroll
            for (int li = 0; li < 2; li++) {
                uint32_t b4[4];
                uint32_t off = ((uint32_t)((nbase + fmb + li * 16) * 2)) ^ swb;
                LDSM4T(b4, rowb + off);
                MMA(c[0][li*2],     ah[0], b4[0], b4[1]);
                MMA(c[1][li*2],     ah[1], b4[0], b4[1]);
                MMA(c[0][li*2 + 1], ah[0], b4[2], b4[3]);
                MMA(c[1][li*2 + 1], ah[1], b4[2], b4[3]);
            }
        }
    }
#pragma unroll
    for (int mi = 0; mi < 2; mi++)
#pragma unroll
        for (int u = 0; u < 2; u++) {
            const int row = bm + mbase + mi * 16 + u * 8 + g;
#pragma unroll
            for (int ng = 0; ng < 4; ng++) {
                const int col = bn + nbase + ng * 8 + 2 * t;
                float2 val;
                val.x = c[mi][ng][u*2 + 0];
                val.y = c[mi][ng][u*2 + 1];
                *(float2*)(g_mapped + (size_t)row * HF + col) = val;
                uint32_t o;
                asm("cvt.rn.bf16x2.f32 %0, %1, %2;" : "=r"(o) : "f"(val.y), "f"(val.x));
                *(uint32_t*)(g_mapped_bf + (size_t)row * HF + col) = o;
            }
        }
}

// ---------------- el/er (pre-scaled by log2e; er transposed) -------------------
__global__ __launch_bounds__(256) void elr_kernel(const float* __restrict__ a) {
    int gid = blockIdx.x * 256 + threadIdx.x;       // over 2*B*N*H
    if (gid >= 2 * BB * NN * HH) return;
    int idx = gid >> 1, half = gid & 1;
    const float4* mp = (const float4*)&g_mapped[(size_t)idx * FF + half * 32];
    const float4* al = (const float4*)(a + half * 32);
    const float4* ar = (const float4*)(a + FF + half * 32);
    float el = 0.f, er = 0.f;
#pragma unroll
    for (int q = 0; q < 8; q++) {
        float4 v = mp[q], x = al[q], y = ar[q];
        el += v.x * x.x + v.y * x.y + v.z * x.z + v.w * x.w;
        er += v.x * y.x + v.y * y.y + v.z * y.z + v.w * y.w;
    }
    el += __shfl_xor_sync(0xffffffffu, el, 1);
    er += __shfl_xor_sync(0xffffffffu, er, 1);
    if (half == 0) {
        int h = idx & (HH - 1);
        int bn = idx >> 3;                 // b*NN + n
        int b = bn >> 11, n = bn & (NN - 1);
        g_el[idx] = el * LOG2E;
        g_er_t[((size_t)h * BB + b) * NN + n] = er * LOG2E;
    }
}

// ---------------- pack edges int32 -> byte -------------------------------------
__global__ __launch_bounds__(256) void pack_edges_kernel(const int* __restrict__ e) {
    size_t base = ((size_t)blockIdx.x * 256 + threadIdx.x) * 16;
    uint32_t out[4];
#pragma unroll
    for (int w = 0; w < 4; w++) {
        int4 v = *(const int4*)(e + base + w * 4);
        out[w] = (v.x ? 1u : 0u) | ((v.y ? 1u : 0u) << 8) |
                 ((v.z ? 1u : 0u) << 16) | ((v.w ? 1u : 0u) << 24);
    }
    uint4 o; o.x = out[0]; o.y = out[1]; o.z = out[2]; o.w = out[3];
    *(uint4*)(g_eb + base) = o;
}

// ---------------- attention: R13 inner loop + cp.async double buffering --------
// grid (16, 2, 8), 256 thr, 8 warps; warp owns 16 i-rows. Two smem buffers of
// the R13 layout (stride 35328). Prefetch tile t+1 while computing tile t.
#define SV   0
#define SEB  16384
#define SER  34816
#define SBUF 35328
#define SM_AT 70656

#define PPAIR(DH, EL, ER2, EU, LACC) do{                                      \
    float e0 = (EL) + (ER2).x, e1 = (EL) + (ER2).y;                           \
    float s0 = fmaxf(e0, 0.2f * e0), s1 = fmaxf(e1, 0.2f * e1);               \
    float p0, p1;                                                             \
    asm("ex2.approx.f32 %0, %1;" : "=f"(p0) : "f"(s0));                       \
    asm("ex2.approx.f32 %0, %1;" : "=f"(p1) : "f"(s1));                       \
    p0 = ((EU) & 0xFFu)   ? p0 : 0.f;                                         \
    p1 = ((EU) & 0xFF00u) ? p1 : 0.f;                                         \
    (LACC) += p0 + p1;                                                        \
    asm("cvt.rn.bf16x2.f32 %0, %1, %2;" : "=r"(DH) : "f"(p1), "f"(p0));       \
} while(0)

__global__ __launch_bounds__(256) void attn_hmma_kernel(void) {
    extern __shared__ char smem[];
    const uint32_t sb = smem_u32(smem);
    const int tid = threadIdx.x, w = tid >> 5, lane = tid & 31;
    const int b = blockIdx.y, i0 = blockIdx.x * 128, head = blockIdx.z;
    const int ib = w * 16;
    const int g = lane >> 2, t = lane & 3;

    float el_r[2];
    el_r[0] = g_el[((size_t)b*NN + i0 + ib + g)*HH + head];
    el_r[1] = g_el[((size_t)b*NN + i0 + ib + 8 + g)*HH + head];

    float c[8][4];
    float l_acc[2] = {0.f, 0.f};
#pragma unroll
    for (int ng = 0; ng < 8; ng++)
#pragma unroll
        for (int r = 0; r < 4; r++) c[ng][r] = 0.f;

    const int joff = ((lane >> 3) & 1) * 8 + (lane & 7);
    const int fmb  = (lane >> 4) * 8;
    const uint32_t sw = (uint32_t)((lane & 7) << 4);

    // staging roles
    const int sj = tid >> 1, shf = (tid & 1);              // V: row, f-half
    const uint32_t swj = (uint32_t)((sj & 7) << 4);
    const char* vsrc0 = (const char*)(g_mapped_bf + ((size_t)b*NN + sj)*HF + head*FF + shf*32);
    const char* esrc0 = (const char*)(g_eb + ((size_t)b*NN + i0 + sj)*NN + shf*64);
    const char* rsrc0 = (const char*)(g_er_t + ((size_t)head*BB + b)*NN) + tid*16;

#define PREFETCH(TT, BUF) do{                                                   \
    const uint32_t bb_ = sb + (BUF)*SBUF;                                       \
    const char* vs = vsrc0 + (size_t)(TT)*128*HF*2;                             \
    _Pragma("unroll")                                                           \
    for (int q8 = 0; q8 < 4; q8++) {                                            \
        uint32_t dst = bb_ + SV + (uint32_t)(sj*128) + (((uint32_t)(shf*64 + q8*16)) ^ swj); \
        CPA16(dst, vs + q8*16);                                                 \
    }                                                                           \
    const char* es = esrc0 + (TT)*128;                                          \
    _Pragma("unroll")                                                           \
    for (int k = 0; k < 4; k++) {                                               \
        uint32_t dst = bb_ + SEB + (uint32_t)(sj*144 + shf*64 + k*16);          \
        CPA16(dst, es + k*16);                                                  \
    }                                                                           \
    if (tid < 32) CPA16(bb_ + SER + tid*16, rsrc0 + (TT)*512);                  \
} while(0)

    PREFETCH(0, 0);
    CPA_COMMIT();

    for (int tt = 0; tt < TILES; tt++) {
        if (tt + 1 < TILES) {
            PREFETCH(tt + 1, (tt + 1) & 1);
            CPA_COMMIT();
            CPA_WAIT1();
        } else {
            CPA_WAIT0();
        }
        __syncthreads();
        const uint32_t bb = sb + (tt & 1)*SBUF;
        const char* smb = smem + (tt & 1)*SBUF;

#pragma unroll
        for (int tk = 0; tk < 8; tk++) {
            const int j0k = tk * 16;
            float2 erA = *(const float2*)(smb + SER + (j0k + 2*t)*4);
            float2 erB = *(const float2*)(smb + SER + (j0k + 8 + 2*t)*4);
            uint32_t ah[4];
            {
                uint32_t ea = bb + SEB + (uint32_t)((ib + g)*144 + j0k + 2*t);
                uint32_t eA0, eA1, eB0, eB1;
                asm volatile("ld.shared.u16 %0, [%1];"     : "=r"(eA0) : "r"(ea));
                asm volatile("ld.shared.u16 %0, [%1+8];"   : "=r"(eA1) : "r"(ea));
                asm volatile("ld.shared.u16 %0, [%1+1152];": "=r"(eB0) : "r"(ea));
                asm volatile("ld.shared.u16 %0, [%1+1160];": "=r"(eB1) : "r"(ea));
                PPAIR(ah[0], el_r[0], erA, eA0, l_acc[0]);
                PPAIR(ah[1], el_r[1], erA, eB0, l_acc[1]);
                PPAIR(ah[2], el_r[0], erB, eA1, l_acc[0]);
                PPAIR(ah[3], el_r[1], erB, eB1, l_acc[1]);
            }
            uint32_t rowb = bb + SV + (uint32_t)(j0k + joff)*128u;
#pragma unroll
            for (int li = 0; li < 4; li++) {
                uint32_t b4[4];
                uint32_t off = ((uint32_t)((fmb + li*16)*2)) ^ sw;
                LDSM4T(b4, rowb + off);
                MMA(c[li*2],     ah, b4[0], b4[1]);
                MMA(c[li*2 + 1], ah, b4[2], b4[3]);
            }
        }
        __syncthreads();
    }

    float linv[2];
#pragma unroll
    for (int k = 0; k < 2; k++) {
        float l = l_acc[k];
        l += __shfl_xor_sync(0xffffffffu, l, 1);
        l += __shfl_xor_sync(0xffffffffu, l, 2);
        linv[k] = 1.f / l;
    }
#pragma unroll
    for (int u = 0; u < 2; u++) {
        const int row = i0 + ib + u*8 + g;
        float* dst = g_hout + (((size_t)b*HH + head)*NN + row)*FF + 2*t;
        const float lv = linv[u];
#pragma unroll
        for (int ng = 0; ng < 8; ng++) {
            float2 val;
            val.x = c[ng][u*2 + 0] * lv;
            val.y = c[ng][u*2 + 1] * lv;
            *(float2*)(dst + ng*8) = val;
        }
    }
}

// ---------------- combine: mean over heads + sigmoid ---------------------------
__global__ __launch_bounds__(256) void combine_kernel(float* __restrict__ out) {
    int idx = blockIdx.x * 256 + threadIdx.x;
    if (idx >= BB * NN * FF) return;
    int f = idx & 63;
    int bi = idx >> 6;
    int b = bi >> 11, i = bi & 2047;
    float s = 0.f;
#pragma unroll
    for (int h = 0; h < HH; h++)
        s += g_hout[(((size_t)b * HH + h) * NN + i) * FF + f];
    s *= 0.125f;
    out[idx] = 1.f / (1.f + __expf(-s));
}

// ---------------- launch -------------------------------------------------------
extern "C" void kernel_launch(void* const* d_in, const int* in_sizes, int n_in,
                              void* d_out, int out_size) {
    const float* nodes = (const float*)d_in[0];
    const int*   edges = (const int*)d_in[1];
    const float* W     = (const float*)d_in[2];
    const float* a     = (const float*)d_in[3];
    float* out = (float*)d_out;

    cudaFuncSetAttribute(attn_hmma_kernel, cudaFuncAttributeMaxDynamicSharedMemorySize,
                         SM_AT);

    cvt_nodes_kernel<<<(BB*NN*DIN/4)/256, 256>>>((const float4*)nodes);
    cvt_w_kernel<<<(DIN*HF/4)/256, 256>>>((const float4*)W);

    dim3 ggrid(HF / 64, (BB * NN) / 128);    // (8, 32) = 256 CTAs
    gemm_hmma_kernel<<<ggrid, 256>>>();

    elr_kernel<<<(2 * BB * NN * HH + 255) / 256, 256>>>(a);

    pack_edges_kernel<<<(BB * NN * NN) / (256 * 16), 256>>>(edges);

    dim3 agrid(NN / 128, BB, HH);            // (16, 2, 8) = 256 CTAs
    attn_hmma_kernel<<<agrid, 256, SM_AT>>>();

    combine_kernel<<<(BB * NN * FF + 255) / 256, 256>>>(out);
}

// round 17
// speedup vs baseline: 1.4506x; 1.0404x over previous
#include <cuda_runtime.h>
#include <cuda_bf16.h>
#include <cstdint>

#define BB 2
#define NN 2048
#define DIN 512
#define HH 8
#define FF 64
#define HF 512
#define TILES 16
#define LOG2E 1.4426950408889634f

__device__ __nv_bfloat16 g_nodes_bf[(size_t)BB*NN*DIN];
__device__ __nv_bfloat16 g_w_bf[DIN*HF];
__device__ __nv_bfloat16 g_mapped_bf[(size_t)BB*NN*HF];
__device__ float g_el[BB*NN*HH];
__device__ float g_er_t[HH*BB*NN];          // transposed: [h][b][n]
__device__ __nv_bfloat16 g_hout_bf[(size_t)BB*HH*NN*FF];
__device__ __align__(16) unsigned char g_eb[(size_t)BB*NN*NN];

__device__ __forceinline__ uint32_t smem_u32(const void* p){
    uint32_t a; asm("{ .reg .u64 t; cvta.to.shared.u64 t, %1; cvt.u32.u64 %0, t; }" : "=r"(a) : "l"(p)); return a;
}

#define MMA(c, a, b0, b1) asm volatile( \
    "mma.sync.aligned.m16n8k16.row.col.f32.bf16.bf16.f32 " \
    "{%0,%1,%2,%3}, {%4,%5,%6,%7}, {%8,%9}, {%0,%1,%2,%3};" \
    : "+f"((c)[0]), "+f"((c)[1]), "+f"((c)[2]), "+f"((c)[3]) \
    : "r"((a)[0]), "r"((a)[1]), "r"((a)[2]), "r"((a)[3]), "r"(b0), "r"(b1))

#define LDSM4(r, addr) asm volatile( \
    "ldmatrix.sync.aligned.m8n8.x4.shared.b16 {%0,%1,%2,%3}, [%4];" \
    : "=r"((r)[0]), "=r"((r)[1]), "=r"((r)[2]), "=r"((r)[3]) : "r"(addr))

#define LDSM4T(r, addr) asm volatile( \
    "ldmatrix.sync.aligned.m8n8.x4.trans.shared.b16 {%0,%1,%2,%3}, [%4];" \
    : "=r"((r)[0]), "=r"((r)[1]), "=r"((r)[2]), "=r"((r)[3]) : "r"(addr))

#define CPA16(dst, src) asm volatile( \
    "cp.async.cg.shared.global [%0], [%1], 16;" :: "r"(dst), "l"(src) : "memory")
#define CPA_COMMIT() asm volatile("cp.async.commit_group;" ::: "memory")
#define CPA_WAIT1() asm volatile("cp.async.wait_group 1;" ::: "memory")
#define CPA_WAIT0() asm volatile("cp.async.wait_group 0;" ::: "memory")

// ---------------- f32 -> bf16 input packs --------------------------------------
__global__ __launch_bounds__(256) void cvt_nodes_kernel(const float4* __restrict__ src) {
    int i = blockIdx.x * 256 + threadIdx.x;
    float4 v = src[i];
    uint2 o;
    asm("cvt.rn.bf16x2.f32 %0, %1, %2;" : "=r"(o.x) : "f"(v.y), "f"(v.x));
    asm("cvt.rn.bf16x2.f32 %0, %1, %2;" : "=r"(o.y) : "f"(v.w), "f"(v.z));
    ((uint2*)g_nodes_bf)[i] = o;
}
__global__ __launch_bounds__(256) void cvt_w_kernel(const float4* __restrict__ src) {
    int i = blockIdx.x * 256 + threadIdx.x;
    float4 v = src[i];
    uint2 o;
    asm("cvt.rn.bf16x2.f32 %0, %1, %2;" : "=r"(o.x) : "f"(v.y), "f"(v.x));
    asm("cvt.rn.bf16x2.f32 %0, %1, %2;" : "=r"(o.y) : "f"(v.w), "f"(v.z));
    ((uint2*)g_w_bf)[i] = o;
}

// ---------------- GEMM + fused el/er -------------------------------------------
// grid (HF/64=8, B*N/128=32). blockIdx.x == head (64-col tile = one head's f).
// Epilogue: bf16 mapped store + per-thread el/er dot with a, quad-shfl reduce,
// smem bounce across the two n-warps, 128 threads write g_el / g_er_t.
__global__ __launch_bounds__(256) void gemm_hmma_kernel(const float* __restrict__ a) {
    __shared__ __align__(16) char smA[16384];
    __shared__ __align__(16) char smB[8192];
    __shared__ float s_el[2][128];
    __shared__ float s_er[2][128];
    const uint32_t sa = smem_u32(smA), sbm = smem_u32(smB);
    const int tid = threadIdx.x, w = tid >> 5, lane = tid & 31;
    const int bn = blockIdx.x * 64, bm = blockIdx.y * 128;
    const int head = blockIdx.x;
    const int mbase = (w & 3) * 32, nbase = (w >> 2) * 32;
    const int g = lane >> 2, t = lane & 3;

    float c[2][4][4];
#pragma unroll
    for (int mi = 0; mi < 2; mi++)
#pragma unroll
        for (int ng = 0; ng < 4; ng++)
#pragma unroll
            for (int r = 0; r < 4; r++) c[mi][ng][r] = 0.f;

    const int arow0 = lane & 15, akh = lane >> 4;
    const int joff = ((lane >> 3) & 1) * 8 + (lane & 7);
    const int fmb  = (lane >> 4) * 8;
    const uint32_t swb = (uint32_t)((lane & 7) << 4);

    for (int kc = 0; kc < 8; kc++) {
        const int k0 = kc * 64;
        __syncthreads();
        {
            const int row = tid >> 1, half = tid & 1;
            const uint4* src = (const uint4*)(g_nodes_bf + (size_t)(bm + row) * DIN + k0 + half * 32);
            uint4 v0 = src[0], v1 = src[1], v2 = src[2], v3 = src[3];
            const uint32_t sw = (uint32_t)((row & 7) << 4);
            char* rbase = smA + row * 128;
            *(uint4*)(rbase + (((uint32_t)(half*64 + 0))  ^ sw)) = v0;
            *(uint4*)(rbase + (((uint32_t)(half*64 + 16)) ^ sw)) = v1;
            *(uint4*)(rbase + (((uint32_t)(half*64 + 32)) ^ sw)) = v2;
            *(uint4*)(rbase + (((uint32_t)(half*64 + 48)) ^ sw)) = v3;
        }
        {
            const int krow = tid >> 2, q4 = tid & 3;
            const uint4* src = (const uint4*)(g_w_bf + (size_t)(k0 + krow) * HF + bn + q4 * 16);
            uint4 v0 = src[0], v1 = src[1];
            const uint32_t sw = (uint32_t)((krow & 7) << 4);
            char* rbase = smB + krow * 128;
            *(uint4*)(rbase + (((uint32_t)(q4*32 + 0))  ^ sw)) = v0;
            *(uint4*)(rbase + (((uint32_t)(q4*32 + 16)) ^ sw)) = v1;
        }
        __syncthreads();

#pragma unroll
        for (int kk = 0; kk < 4; kk++) {
            uint32_t ah[2][4];
#pragma unroll
            for (int mi = 0; mi < 2; mi++) {
                const int arow = mbase + mi * 16 + arow0;
                uint32_t addr = sa + (uint32_t)arow * 128u +
                    (((uint32_t)(kk * 32 + akh * 16)) ^ ((uint32_t)(arow & 7) << 4));
                LDSM4(ah[mi], addr);
            }
            uint32_t rowb = sbm + (uint32_t)(kk * 16 + joff) * 128u;
#pragma unroll
            for (int li = 0; li < 2; li++) {
                uint32_t b4[4];
                uint32_t off = ((uint32_t)((nbase + fmb + li * 16) * 2)) ^ swb;
                LDSM4T(b4, rowb + off);
                MMA(c[0][li*2],     ah[0], b4[0], b4[1]);
                MMA(c[1][li*2],     ah[1], b4[0], b4[1]);
                MMA(c[0][li*2 + 1], ah[0], b4[2], b4[3]);
                MMA(c[1][li*2 + 1], ah[1], b4[2], b4[3]);
            }
        }
    }
    // ---- epilogue: bf16 mapped + fused el/er ----
    float alv[4][2], arv[4][2];
#pragma unroll
    for (int ng = 0; ng < 4; ng++)
#pragma unroll
        for (int k = 0; k < 2; k++) {
            int f = nbase + ng * 8 + 2 * t + k;
            alv[ng][k] = a[f];
            arv[ng][k] = a[FF + f];
        }
    float elp[2][2], erp[2][2];
#pragma unroll
    for (int mi = 0; mi < 2; mi++)
#pragma unroll
        for (int u = 0; u < 2; u++) { elp[mi][u] = 0.f; erp[mi][u] = 0.f; }
#pragma unroll
    for (int mi = 0; mi < 2; mi++)
#pragma unroll
        for (int u = 0; u < 2; u++) {
            const int row = bm + mbase + mi * 16 + u * 8 + g;
#pragma unroll
            for (int ng = 0; ng < 4; ng++) {
                const int col = bn + nbase + ng * 8 + 2 * t;
                float vx = c[mi][ng][u*2 + 0], vy = c[mi][ng][u*2 + 1];
                uint32_t o;
                asm("cvt.rn.bf16x2.f32 %0, %1, %2;" : "=r"(o) : "f"(vy), "f"(vx));
                *(uint32_t*)(g_mapped_bf + (size_t)row * HF + col) = o;
                elp[mi][u] += vx * alv[ng][0] + vy * alv[ng][1];
                erp[mi][u] += vx * arv[ng][0] + vy * arv[ng][1];
            }
        }
#pragma unroll
    for (int mi = 0; mi < 2; mi++)
#pragma unroll
        for (int u = 0; u < 2; u++) {
            float e = elp[mi][u], r = erp[mi][u];
            e += __shfl_xor_sync(0xffffffffu, e, 1);
            e += __shfl_xor_sync(0xffffffffu, e, 2);
            r += __shfl_xor_sync(0xffffffffu, r, 1);
            r += __shfl_xor_sync(0xffffffffu, r, 2);
            if (t == 0) {
                int rl = mbase + mi * 16 + u * 8 + g;
                s_el[w >> 2][rl] = e;
                s_er[w >> 2][rl] = r;
            }
        }
    __syncthreads();
    if (tid < 128) {
        float e = (s_el[0][tid] + s_el[1][tid]) * LOG2E;
        float r = (s_er[0][tid] + s_er[1][tid]) * LOG2E;
        int b = bm >> 11;
        int n = (bm & (NN - 1)) + tid;
        g_el[((size_t)b * NN + n) * HH + head] = e;
        g_er_t[((size_t)head * BB + b) * NN + n] = r;
    }
}

// ---------------- pack edges int32 -> byte -------------------------------------
__global__ __launch_bounds__(256) void pack_edges_kernel(const int* __restrict__ e) {
    size_t base = ((size_t)blockIdx.x * 256 + threadIdx.x) * 16;
    uint32_t out[4];
#pragma unroll
    for (int w = 0; w < 4; w++) {
        int4 v = *(const int4*)(e + base + w * 4);
        out[w] = (v.x ? 1u : 0u) | ((v.y ? 1u : 0u) << 8) |
                 ((v.z ? 1u : 0u) << 16) | ((v.w ? 1u : 0u) << 24);
    }
    uint4 o; o.x = out[0]; o.y = out[1]; o.z = out[2]; o.w = out[3];
    *(uint4*)(g_eb + base) = o;
}

// ---------------- attention: pipelined (frozen R16 core), bf16 hout ------------
#define SV   0
#define SEB  16384
#define SER  34816
#define SBUF 35328
#define SM_AT 70656

#define PPAIR(DH, EL, ER2, EU, LACC) do{                                      \
    float e0 = (EL) + (ER2).x, e1 = (EL) + (ER2).y;                           \
    float s0 = fmaxf(e0, 0.2f * e0), s1 = fmaxf(e1, 0.2f * e1);               \
    float p0, p1;                                                             \
    asm("ex2.approx.f32 %0, %1;" : "=f"(p0) : "f"(s0));                       \
    asm("ex2.approx.f32 %0, %1;" : "=f"(p1) : "f"(s1));                       \
    p0 = ((EU) & 0xFFu)   ? p0 : 0.f;                                         \
    p1 = ((EU) & 0xFF00u) ? p1 : 0.f;                                         \
    (LACC) += p0 + p1;                                                        \
    asm("cvt.rn.bf16x2.f32 %0, %1, %2;" : "=r"(DH) : "f"(p1), "f"(p0));       \
} while(0)

__global__ __launch_bounds__(256) void attn_hmma_kernel(void) {
    extern __shared__ char smem[];
    const uint32_t sb = smem_u32(smem);
    const int tid = threadIdx.x, w = tid >> 5, lane = tid & 31;
    const int b = blockIdx.y, i0 = blockIdx.x * 128, head = blockIdx.z;
    const int ib = w * 16;
    const int g = lane >> 2, t = lane & 3;

    float el_r[2];
    el_r[0] = g_el[((size_t)b*NN + i0 + ib + g)*HH + head];
    el_r[1] = g_el[((size_t)b*NN + i0 + ib + 8 + g)*HH + head];

    float c[8][4];
    float l_acc[2] = {0.f, 0.f};
#pragma unroll
    for (int ng = 0; ng < 8; ng++)
#pragma unroll
        for (int r = 0; r < 4; r++) c[ng][r] = 0.f;

    const int joff = ((lane >> 3) & 1) * 8 + (lane & 7);
    const int fmb  = (lane >> 4) * 8;
    const uint32_t sw = (uint32_t)((lane & 7) << 4);

    const int sj = tid >> 1, shf = (tid & 1);
    const uint32_t swj = (uint32_t)((sj & 7) << 4);
    const char* vsrc0 = (const char*)(g_mapped_bf + ((size_t)b*NN + sj)*HF + head*FF + shf*32);
    const char* esrc0 = (const char*)(g_eb + ((size_t)b*NN + i0 + sj)*NN + shf*64);
    const char* rsrc0 = (const char*)(g_er_t + ((size_t)head*BB + b)*NN) + tid*16;

#define PREFETCH(TT, BUF) do{                                                   \
    const uint32_t bb_ = sb + (BUF)*SBUF;                                       \
    const char* vs = vsrc0 + (size_t)(TT)*128*HF*2;                             \
    _Pragma("unroll")                                                           \
    for (int q8 = 0; q8 < 4; q8++) {                                            \
        uint32_t dst = bb_ + SV + (uint32_t)(sj*128) + (((uint32_t)(shf*64 + q8*16)) ^ swj); \
        CPA16(dst, vs + q8*16);                                                 \
    }                                                                           \
    const char* es = esrc0 + (TT)*128;                                          \
    _Pragma("unroll")                                                           \
    for (int k = 0; k < 4; k++) {                                               \
        uint32_t dst = bb_ + SEB + (uint32_t)(sj*144 + shf*64 + k*16);          \
        CPA16(dst, es + k*16);                                                  \
    }                                                                           \
    if (tid < 32) CPA16(bb_ + SER + tid*16, rsrc0 + (TT)*512);                  \
} while(0)

    PREFETCH(0, 0);
    CPA_COMMIT();

    for (int tt = 0; tt < TILES; tt++) {
        if (tt + 1 < TILES) {
            PREFETCH(tt + 1, (tt + 1) & 1);
            CPA_COMMIT();
            CPA_WAIT1();
        } else {
            CPA_WAIT0();
        }
        __syncthreads();
        const uint32_t bb = sb + (tt & 1)*SBUF;
        const char* smb = smem + (tt & 1)*SBUF;

#pragma unroll
        for (int tk = 0; tk < 8; tk++) {
            const int j0k = tk * 16;
            float2 erA = *(const float2*)(smb + SER + (j0k + 2*t)*4);
            float2 erB = *(const float2*)(smb + SER + (j0k + 8 + 2*t)*4);
            uint32_t ah[4];
            {
                uint32_t ea = bb + SEB + (uint32_t)((ib + g)*144 + j0k + 2*t);
                uint32_t eA0, eA1, eB0, eB1;
                asm volatile("ld.shared.u16 %0, [%1];"     : "=r"(eA0) : "r"(ea));
                asm volatile("ld.shared.u16 %0, [%1+8];"   : "=r"(eA1) : "r"(ea));
                asm volatile("ld.shared.u16 %0, [%1+1152];": "=r"(eB0) : "r"(ea));
                asm volatile("ld.shared.u16 %0, [%1+1160];": "=r"(eB1) : "r"(ea));
                PPAIR(ah[0], el_r[0], erA, eA0, l_acc[0]);
                PPAIR(ah[1], el_r[1], erA, eB0, l_acc[1]);
                PPAIR(ah[2], el_r[0], erB, eA1, l_acc[0]);
                PPAIR(ah[3], el_r[1], erB, eB1, l_acc[1]);
            }
            uint32_t rowb = bb + SV + (uint32_t)(j0k + joff)*128u;
#pragma unroll
            for (int li = 0; li < 4; li++) {
                uint32_t b4[4];
                uint32_t off = ((uint32_t)((fmb + li*16)*2)) ^ sw;
                LDSM4T(b4, rowb + off);
                MMA(c[li*2],     ah, b4[0], b4[1]);
                MMA(c[li*2 + 1], ah, b4[2], b4[3]);
            }
        }
        __syncthreads();
    }

    float linv[2];
#pragma unroll
    for (int k = 0; k < 2; k++) {
        float l = l_acc[k];
        l += __shfl_xor_sync(0xffffffffu, l, 1);
        l += __shfl_xor_sync(0xffffffffu, l, 2);
        linv[k] = 1.f / l;
    }
#pragma unroll
    for (int u = 0; u < 2; u++) {
        const int row = i0 + ib + u*8 + g;
        __nv_bfloat16* dst = g_hout_bf + (((size_t)b*HH + head)*NN + row)*FF + 2*t;
        const float lv = linv[u];
#pragma unroll
        for (int ng = 0; ng < 8; ng++) {
            float vx = c[ng][u*2 + 0] * lv;
            float vy = c[ng][u*2 + 1] * lv;
            uint32_t o;
            asm("cvt.rn.bf16x2.f32 %0, %1, %2;" : "=r"(o) : "f"(vy), "f"(vx));
            *(uint32_t*)(dst + ng*8) = o;
        }
    }
}

// ---------------- combine: bf16 pairs, mean over heads + sigmoid ---------------
__global__ __launch_bounds__(256) void combine_kernel(float* __restrict__ out) {
    int idx = blockIdx.x * 256 + threadIdx.x;       // over B*N*32 f-pairs
    if (idx >= BB * NN * (FF/2)) return;
    int p  = idx & 31;
    int bi = idx >> 5;                              // b*NN + n
    int b  = bi >> 11;
    int n  = bi & (NN - 1);
    float s0 = 0.f, s1 = 0.f;
#pragma unroll
    for (int h = 0; h < HH; h++) {
        uint32_t u = *(const uint32_t*)(g_hout_bf +
            (((size_t)b * HH + h) * NN + n) * FF + p * 2);
        s0 += __uint_as_float(u << 16);
        s1 += __uint_as_float(u & 0xFFFF0000u);
    }
    s0 *= 0.125f; s1 *= 0.125f;
    float2 o;
    o.x = 1.f / (1.f + __expf(-s0));
    o.y = 1.f / (1.f + __expf(-s1));
    *(float2*)(out + (size_t)bi * FF + p * 2) = o;
}

// ---------------- launch -------------------------------------------------------
extern "C" void kernel_launch(void* const* d_in, const int* in_sizes, int n_in,
                              void* d_out, int out_size) {
    const float* nodes = (const float*)d_in[0];
    const int*   edges = (const int*)d_in[1];
    const float* W     = (const float*)d_in[2];
    const float* a     = (const float*)d_in[3];
    float* out = (float*)d_out;

    cudaFuncSetAttribute(attn_hmma_kernel, cudaFuncAttributeMaxDynamicSharedMemorySize,
                         SM_AT);

    cvt_nodes_kernel<<<(BB*NN*DIN/4)/256, 256>>>((const float4*)nodes);
    cvt_w_kernel<<<(DIN*HF/4)/256, 256>>>((const float4*)W);

    dim3 ggrid(HF / 64, (BB * NN) / 128);    // (8, 32) = 256 CTAs
    gemm_hmma_kernel<<<ggrid, 256>>>(a);

    pack_edges_kernel<<<(BB * NN * NN) / (256 * 16), 256>>>(edges);

    dim3 agrid(NN / 128, BB, HH);            // (16, 2, 8) = 256 CTAs
    attn_hmma_kernel<<<agrid, 256, SM_AT>>>();

    combine_kernel<<<(BB * NN * (FF/2) + 255) / 256, 256>>>(out);
}